// round 1
// baseline (speedup 1.0000x reference)
#include <cuda_runtime.h>
#include <cuda_bf16.h>

// Problem shape (fixed by dataset): disp [4,1,1024,1280] f32, kernel_raw [4,8,1024,1280] f32
#define BB    4
#define HH    1024
#define WW    1280
#define PLANE (HH * WW)        // 1310720
#define NPIX  (BB * PLANE)     // 5242880
#define WQ    (WW / 4)         // 320 float4 per row
#define NQ    (NPIX / 4)       // 1310720 quads
#define NITER 24

// Scratch (allocations are forbidden; __device__ globals are the sanctioned path)
__device__ float g_w[(size_t)8 * NPIX];   // normalized affinity weights, planar [8][B*H*W]
__device__ float g_ping[NPIX];            // ping-pong disparity buffer

// ---------------------------------------------------------------------------
// Pass 1: normalize kernel_raw once.
//   norm[c] = raw[c] / (sum_c |raw[c]| + 1e-9)
// Stored planar so the stencil kernel reads 8 coalesced float4 streams.
// Center weight (1 - sum) is reconstructed in the stencil kernel (saves 20MB/iter).
// ---------------------------------------------------------------------------
__global__ void __launch_bounds__(256) prep_kernel(const float* __restrict__ raw) {
    int q = blockIdx.x * 256 + threadIdx.x;
    if (q >= NQ) return;
    int b = q / (PLANE / 4);
    int r = q - b * (PLANE / 4);
    // raw layout [B][8][H][W]
    const float4* base = reinterpret_cast<const float4*>(raw) + (size_t)b * 8 * (PLANE / 4) + r;

    float4 v[8];
    float sx = 0.f, sy = 0.f, sz = 0.f, sw = 0.f;
#pragma unroll
    for (int c = 0; c < 8; c++) {
        v[c] = base[(size_t)c * (PLANE / 4)];
        sx += fabsf(v[c].x); sy += fabsf(v[c].y);
        sz += fabsf(v[c].z); sw += fabsf(v[c].w);
    }
    float ix = __frcp_rn(sx + 1e-9f);
    float iy = __frcp_rn(sy + 1e-9f);
    float iz = __frcp_rn(sz + 1e-9f);
    float iw = __frcp_rn(sw + 1e-9f);

    float4* wout = reinterpret_cast<float4*>(g_w);
#pragma unroll
    for (int c = 0; c < 8; c++) {
        float4 o;
        o.x = v[c].x * ix; o.y = v[c].y * iy;
        o.z = v[c].z * iz; o.w = v[c].w * iw;
        wout[(size_t)c * NQ + q] = o;
    }
}

// ---------------------------------------------------------------------------
// Pass 2 (x24): refined[y,x] = w0*d[y,x] + sum_{c=0..7} w[c]*d[y-i_c, x-j_c]
// OFFSETS (after center): (1,1)(1,0)(1,-1)(0,-1)(-1,-1)(-1,0)(-1,1)(0,1)
// i.e. raw channel c reads d at:
//   c0:(y-1,x-1) c1:(y-1,x) c2:(y-1,x+1) c3:(y,x+1)
//   c4:(y+1,x+1) c5:(y+1,x) c6:(y+1,x-1) c7:(y,x-1)
// Zero padding at image borders. Each thread computes 4 consecutive x pixels.
// ---------------------------------------------------------------------------
template <bool CLIP>
__global__ void __launch_bounds__(256) step_kernel(const float* __restrict__ din,
                                                   float* __restrict__ dout) {
    int q = blockIdx.x * 256 + threadIdx.x;
    if (q >= NQ) return;

    int rowg = q / WQ;           // global row in [0, B*H)
    int xq   = q - rowg * WQ;    // quad index within row
    int y    = rowg & (HH - 1);  // row within image (H is pow2)
    int pix  = rowg * WW + xq * 4;

    const float4* d4 = reinterpret_cast<const float4*>(din);

    float t6[6], m6[6], b6[6];   // [x-1, x, x+1, x+2, x+3, x+4] for top/mid/bottom rows

    float4 mv = d4[q];
    m6[1] = mv.x; m6[2] = mv.y; m6[3] = mv.z; m6[4] = mv.w;
    m6[0] = (xq > 0)      ? __ldg(din + pix - 1) : 0.f;
    m6[5] = (xq < WQ - 1) ? __ldg(din + pix + 4) : 0.f;

    if (y > 0) {
        float4 tv = d4[q - WQ];
        t6[1] = tv.x; t6[2] = tv.y; t6[3] = tv.z; t6[4] = tv.w;
        t6[0] = (xq > 0)      ? __ldg(din + pix - WW - 1) : 0.f;
        t6[5] = (xq < WQ - 1) ? __ldg(din + pix - WW + 4) : 0.f;
    } else {
#pragma unroll
        for (int i = 0; i < 6; i++) t6[i] = 0.f;
    }

    if (y < HH - 1) {
        float4 bv = d4[q + WQ];
        b6[1] = bv.x; b6[2] = bv.y; b6[3] = bv.z; b6[4] = bv.w;
        b6[0] = (xq > 0)      ? __ldg(din + pix + WW - 1) : 0.f;
        b6[5] = (xq < WQ - 1) ? __ldg(din + pix + WW + 4) : 0.f;
    } else {
#pragma unroll
        for (int i = 0; i < 6; i++) b6[i] = 0.f;
    }

    // 8 coalesced weight streams
    float4 wv[8];
    const float4* w4 = reinterpret_cast<const float4*>(g_w);
#pragma unroll
    for (int c = 0; c < 8; c++) wv[c] = w4[(size_t)c * NQ + q];

    float res[4];
#pragma unroll
    for (int p = 0; p < 4; p++) {
        float w[8];
#pragma unroll
        for (int c = 0; c < 8; c++) w[c] = reinterpret_cast<const float*>(&wv[c])[p];

        float s  = ((w[0] + w[1]) + (w[2] + w[3])) + ((w[4] + w[5]) + (w[6] + w[7]));
        float w0 = 1.0f - s;

        float acc = w0 * m6[p + 1];
        acc = fmaf(w[0], t6[p],     acc);  // (1,1)  -> (y-1, x-1)
        acc = fmaf(w[1], t6[p + 1], acc);  // (1,0)  -> (y-1, x)
        acc = fmaf(w[2], t6[p + 2], acc);  // (1,-1) -> (y-1, x+1)
        acc = fmaf(w[3], m6[p + 2], acc);  // (0,-1) -> (y,   x+1)
        acc = fmaf(w[4], b6[p + 2], acc);  // (-1,-1)-> (y+1, x+1)
        acc = fmaf(w[5], b6[p + 1], acc);  // (-1,0) -> (y+1, x)
        acc = fmaf(w[6], b6[p],     acc);  // (-1,1) -> (y+1, x-1)
        acc = fmaf(w[7], m6[p],     acc);  // (0,1)  -> (y,   x-1)

        if (CLIP) acc = fminf(fmaxf(acc, 0.0f), 256.0f);
        res[p] = acc;
    }

    float4 o;
    o.x = res[0]; o.y = res[1]; o.z = res[2]; o.w = res[3];
    reinterpret_cast<float4*>(dout)[q] = o;
}

// ---------------------------------------------------------------------------
extern "C" void kernel_launch(void* const* d_in, const int* in_sizes, int n_in,
                              void* d_out, int out_size) {
    const float* disp = (const float*)d_in[0];
    const float* raw  = (const float*)d_in[1];
    // Defensive: disp has 5.24M elems, kernel_raw 41.9M — swap if order unexpected.
    if (n_in >= 2 && in_sizes[0] > in_sizes[1]) {
        const float* t = disp; disp = raw; raw = t;
    }
    float* out = (float*)d_out;

    float* ping = nullptr;
    cudaGetSymbolAddress((void**)&ping, g_ping);  // address query only; capture-safe

    dim3 block(256);
    dim3 grid((NQ + 255) / 256);

    prep_kernel<<<grid, block>>>(raw);

    // 24 iterations, ping-pong so the final (even) iteration lands in d_out.
    step_kernel<false><<<grid, block>>>(disp, ping);          // it 1 -> ping
    for (int it = 2; it <= NITER - 1; ++it) {
        if ((it & 1) == 0) step_kernel<false><<<grid, block>>>(ping, out);
        else               step_kernel<false><<<grid, block>>>(out, ping);
    }
    step_kernel<true><<<grid, block>>>(ping, out);            // it 24 -> d_out, fused clip
}

// round 2
// speedup vs baseline: 1.6663x; 1.6663x over previous
#include <cuda_runtime.h>
#include <cuda_bf16.h>

// Shape fixed by dataset: disp [4,1,1024,1280] f32, kernel_raw [4,8,1024,1280] f32
#define BB    4
#define HH    1024
#define WW    1280
#define PLANE (HH * WW)
#define NPIX  (BB * PLANE)     // 5242880
#define NQ    (NPIX / 4)
#define NITER 24

// Temporal blocking: T=4 iterations fused per pass, 6 passes.
#define TT    4                // fused iterations
#define TS    56               // output tile (TS = RS - 2*TT)
#define RS    64               // region tile (with halo)
#define SSTR  68               // smem row stride (floats)
#define NTX   ((WW + TS - 1) / TS)   // 23
#define NTY   ((HH + TS - 1) / TS)   // 19

__device__ float g_w[(size_t)8 * NPIX];   // normalized weights, planar [8][B*H*W]
__device__ float g_ping[NPIX];            // ping-pong disparity buffer

// ---------------------------------------------------------------------------
// Pass 1: normalize kernel_raw once. norm[c] = raw[c] / (sum|raw| + 1e-9).
// Center weight (1 - sum) is reconstructed downstream.
// ---------------------------------------------------------------------------
__global__ void __launch_bounds__(256) prep_kernel(const float* __restrict__ raw) {
    int q = blockIdx.x * 256 + threadIdx.x;
    if (q >= NQ) return;
    int b = q / (PLANE / 4);
    int r = q - b * (PLANE / 4);
    const float4* base = reinterpret_cast<const float4*>(raw) + (size_t)b * 8 * (PLANE / 4) + r;

    float4 v[8];
    float sx = 0.f, sy = 0.f, sz = 0.f, sw = 0.f;
#pragma unroll
    for (int c = 0; c < 8; c++) {
        v[c] = base[(size_t)c * (PLANE / 4)];
        sx += fabsf(v[c].x); sy += fabsf(v[c].y);
        sz += fabsf(v[c].z); sw += fabsf(v[c].w);
    }
    float ix = __frcp_rn(sx + 1e-9f);
    float iy = __frcp_rn(sy + 1e-9f);
    float iz = __frcp_rn(sz + 1e-9f);
    float iw = __frcp_rn(sw + 1e-9f);

    float4* wout = reinterpret_cast<float4*>(g_w);
#pragma unroll
    for (int c = 0; c < 8; c++) {
        float4 o;
        o.x = v[c].x * ix; o.y = v[c].y * iy;
        o.z = v[c].z * iz; o.w = v[c].w * iw;
        wout[(size_t)c * NQ + q] = o;
    }
}

// ---------------------------------------------------------------------------
// Fused stencil pass: 4 iterations of
//   d'[y,x] = (1-Σw)*d[y,x] + Σ_c w_c * d[neighbor_c]
// per launch, via trapezoidal temporal blocking.
//   - Each CTA: 64x64 region -> 56x56 output, 512 threads, 8 px/thread (row octet)
//   - Per-pixel weights live in REGISTERS (loaded once per pass, reused 4x)
//   - Disparity ping-pongs in smem; out-of-image px have zero weights -> stay 0,
//     exactly reproducing per-iteration zero padding.
//   - Region-edge px are stored unchanged; their values are only consumed while
//     still valid (iteration t reads only distance>=t-1 pixels).
// ---------------------------------------------------------------------------
template <bool CLIP>
__global__ void __launch_bounds__(512) fused_kernel(const float* __restrict__ din,
                                                    float* __restrict__ dout) {
    __shared__ float sA[RS * SSTR];
    __shared__ float sB[RS * SSTR];

    const int tid = threadIdx.x;
    const int r   = tid >> 3;        // region row 0..63
    const int c   = tid & 7;         // octet 0..7
    const int x0  = c << 3;          // region col of first px

    const int b   = blockIdx.z;
    const int gy  = blockIdx.y * TS - TT + r;      // global row (may be out of image)
    const int gxb = blockIdx.x * TS - TT + x0;     // global col of px0 (mult of 4)

    const bool rowIn = (gy >= 0) && (gy < HH);

    // ---- load disparity region (zero outside image) ----
#pragma unroll
    for (int k = 0; k < 2; k++) {
        int gx = gxb + 4 * k;
        float4 v = make_float4(0.f, 0.f, 0.f, 0.f);
        if (rowIn && gx >= 0 && gx < WW)
            v = *reinterpret_cast<const float4*>(din + (size_t)(b * HH + gy) * WW + gx);
        *reinterpret_cast<float4*>(&sA[r * SSTR + x0 + 4 * k]) = v;
    }

    // ---- load per-pixel weights into registers (zero outside image) ----
    float w[8][8];                   // [channel][px]
#pragma unroll
    for (int ch = 0; ch < 8; ch++) {
#pragma unroll
        for (int k = 0; k < 2; k++) {
            int gx = gxb + 4 * k;
            float4 v = make_float4(0.f, 0.f, 0.f, 0.f);
            if (rowIn && gx >= 0 && gx < WW)
                v = *reinterpret_cast<const float4*>(
                        g_w + (size_t)ch * NPIX + (size_t)(b * HH + gy) * WW + gx);
            w[ch][4 * k + 0] = v.x; w[ch][4 * k + 1] = v.y;
            w[ch][4 * k + 2] = v.z; w[ch][4 * k + 3] = v.w;
        }
    }
    float w0[8];
#pragma unroll
    for (int p = 0; p < 8; p++) {
        float s = ((w[0][p] + w[1][p]) + (w[2][p] + w[3][p])) +
                  ((w[4][p] + w[5][p]) + (w[6][p] + w[7][p]));
        w0[p] = 1.0f - s;
    }

    __syncthreads();

    const bool act = (r >= 1) && (r < RS - 1);
    float res[8];

    // one stencil iteration reading `cur`; results into res[]
    auto compute = [&](const float* __restrict__ cur) {
        float tm[10], mm[10], bm[10];
        const float* tb = cur + (r - 1) * SSTR + x0;
        const float* mb = cur + (r    ) * SSTR + x0;
        const float* bb = cur + (r + 1) * SSTR + x0;
        float4 a, d;
        a = *reinterpret_cast<const float4*>(tb);
        d = *reinterpret_cast<const float4*>(tb + 4);
        tm[1]=a.x; tm[2]=a.y; tm[3]=a.z; tm[4]=a.w;
        tm[5]=d.x; tm[6]=d.y; tm[7]=d.z; tm[8]=d.w;
        tm[0]=tb[-1]; tm[9]=tb[8];
        a = *reinterpret_cast<const float4*>(mb);
        d = *reinterpret_cast<const float4*>(mb + 4);
        mm[1]=a.x; mm[2]=a.y; mm[3]=a.z; mm[4]=a.w;
        mm[5]=d.x; mm[6]=d.y; mm[7]=d.z; mm[8]=d.w;
        mm[0]=mb[-1]; mm[9]=mb[8];
        a = *reinterpret_cast<const float4*>(bb);
        d = *reinterpret_cast<const float4*>(bb + 4);
        bm[1]=a.x; bm[2]=a.y; bm[3]=a.z; bm[4]=a.w;
        bm[5]=d.x; bm[6]=d.y; bm[7]=d.z; bm[8]=d.w;
        bm[0]=bb[-1]; bm[9]=bb[8];

#pragma unroll
        for (int p = 0; p < 8; p++) {
            float acc = w0[p] * mm[p + 1];
            acc = fmaf(w[0][p], tm[p],     acc);  // (y-1,x-1)
            acc = fmaf(w[1][p], tm[p + 1], acc);  // (y-1,x  )
            acc = fmaf(w[2][p], tm[p + 2], acc);  // (y-1,x+1)
            acc = fmaf(w[3][p], mm[p + 2], acc);  // (y  ,x+1)
            acc = fmaf(w[4][p], bm[p + 2], acc);  // (y+1,x+1)
            acc = fmaf(w[5][p], bm[p + 1], acc);  // (y+1,x  )
            acc = fmaf(w[6][p], bm[p],     acc);  // (y+1,x-1)
            acc = fmaf(w[7][p], mm[p],     acc);  // (y  ,x-1)
            res[p] = acc;
        }
        // region-edge columns: keep old value (only ever read while still valid)
        if (x0 + 0 == 0)      res[0] = mm[1];
        if (x0 + 7 == RS - 1) res[7] = mm[8];
    };

    // iterations 0..2 -> smem ping-pong
#pragma unroll
    for (int it = 0; it < TT - 1; it++) {
        const float* cur = (it & 1) ? sB : sA;
        float*       nxt = (it & 1) ? sA : sB;
        if (act) {
            compute(cur);
            float4 o0 = make_float4(res[0], res[1], res[2], res[3]);
            float4 o1 = make_float4(res[4], res[5], res[6], res[7]);
            *reinterpret_cast<float4*>(&nxt[r * SSTR + x0])     = o0;
            *reinterpret_cast<float4*>(&nxt[r * SSTR + x0 + 4]) = o1;
        }
        __syncthreads();
    }

    // iteration 3: compute from sB (after 3 iters state is in sB) and write global
    if (act && r >= TT && r < RS - TT && gy < HH) {
        compute(sB);
        if (CLIP) {
#pragma unroll
            for (int p = 0; p < 8; p++) res[p] = fminf(fmaxf(res[p], 0.f), 256.f);
        }
        size_t orow = (size_t)(b * HH + gy) * WW;
        // output region cols [4,60): c==0 -> px 4..7, c==7 -> px 0..3, else both quads
        if (c != 7) {  // second quad: region cols x0+4..x0+7, all >=4 when c>=0... (c==0 ok)
            int gx = gxb + 4;
            if (gx < WW)
                *reinterpret_cast<float4*>(dout + orow + gx) =
                    make_float4(res[4], res[5], res[6], res[7]);
        }
        if (c != 0) {  // first quad: region cols x0..x0+3, valid when c>=1 (>=8>4); c==7 gives cols 56..59 <60
            int gx = gxb;
            if (gx < WW)
                *reinterpret_cast<float4*>(dout + orow + gx) =
                    make_float4(res[0], res[1], res[2], res[3]);
        }
    }
}

// ---------------------------------------------------------------------------
extern "C" void kernel_launch(void* const* d_in, const int* in_sizes, int n_in,
                              void* d_out, int out_size) {
    const float* disp = (const float*)d_in[0];
    const float* raw  = (const float*)d_in[1];
    if (n_in >= 2 && in_sizes[0] > in_sizes[1]) {  // defensive order check
        const float* t = disp; disp = raw; raw = t;
    }
    float* out = (float*)d_out;

    float* ping = nullptr;
    cudaGetSymbolAddress((void**)&ping, g_ping);  // address query; capture-safe

    prep_kernel<<<(NQ + 255) / 256, 256>>>(raw);

    dim3 grid(NTX, NTY, BB);
    // 6 fused passes x 4 iterations = 24
    fused_kernel<false><<<grid, 512>>>(disp, ping);
    fused_kernel<false><<<grid, 512>>>(ping, out);
    fused_kernel<false><<<grid, 512>>>(out,  ping);
    fused_kernel<false><<<grid, 512>>>(ping, out);
    fused_kernel<false><<<grid, 512>>>(out,  ping);
    fused_kernel<true ><<<grid, 512>>>(ping, out);
}